// round 1
// baseline (speedup 1.0000x reference)
#include <cuda_runtime.h>
#include <cuda_bf16.h>

// Problem shapes (EfficientReynoldsFeatureOperator):
//   x:  (B=8, N=8192, D=512) fp32
//   W:  (D=512, R=128)       fp32
//   pw: (R=128)              fp32
//   out:(B, N, R)            fp32,  out[b,n,r] = (mean_n(x[b]) @ W)[r] * pw[r]
//
// mean_n(x @ W) == (mean_n x) @ W, so we never materialize x_proj.

#define B_DIM 8
#define N_DIM 8192
#define D_DIM 512
#define R_DIM 128
#define CHUNKS 128                 // n-chunks per batch for the reduction
#define ROWS_PER_CHUNK (N_DIM / CHUNKS)   // 64

// Scratch (allocation-free): partial sums + final per-(b,r) values
__device__ float g_partial[B_DIM * CHUNKS * D_DIM];   // 2 MB
__device__ float g_y[B_DIM * R_DIM];                  // 4 KB

// ---------------------------------------------------------------------------
// K1: partial column sums of x over n.
// grid = (CHUNKS, B), block = 128 threads; thread t owns float4 d-slot t.
// Each iteration the block reads a contiguous 2KB row of x -> fully coalesced.
// ---------------------------------------------------------------------------
__global__ __launch_bounds__(128) void k1_colsum_partial(const float* __restrict__ x) {
    const int chunk = blockIdx.x;
    const int b     = blockIdx.y;
    const int d4    = threadIdx.x;            // 0..127, float4 index over D

    const float4* xrow = reinterpret_cast<const float4*>(
        x + (size_t)(b * N_DIM + chunk * ROWS_PER_CHUNK) * D_DIM);

    float4 acc = make_float4(0.f, 0.f, 0.f, 0.f);
#pragma unroll 4
    for (int i = 0; i < ROWS_PER_CHUNK; ++i) {
        float4 v = xrow[(size_t)i * (D_DIM / 4) + d4];
        acc.x += v.x; acc.y += v.y; acc.z += v.z; acc.w += v.w;
    }

    float4* p = reinterpret_cast<float4*>(
        g_partial + (size_t)(b * CHUNKS + chunk) * D_DIM);
    p[d4] = acc;
}

// ---------------------------------------------------------------------------
// K2: per batch, finish the reduction, then y[b,r] = (mean @ W)[r] * pw[r].
// grid = B, block = 512 threads.
// ---------------------------------------------------------------------------
__global__ __launch_bounds__(512) void k2_finish_and_project(
    const float* __restrict__ W, const float* __restrict__ pw) {
    __shared__ float s_mean[D_DIM];
    const int b = blockIdx.x;
    const int t = threadIdx.x;                 // 0..511 -> one d per thread

    // Sum the 128 partials for column d (coalesced across threads).
    float s = 0.f;
    const float* base = g_partial + (size_t)b * CHUNKS * D_DIM + t;
#pragma unroll 8
    for (int c = 0; c < CHUNKS; ++c)
        s += base[(size_t)c * D_DIM];
    s_mean[t] = s * (1.0f / (float)N_DIM);
    __syncthreads();

    // Projection: threads 0..127 each compute one r.
    if (t < R_DIM) {
        float acc = 0.f;
#pragma unroll 8
        for (int d = 0; d < D_DIM; ++d)
            acc = fmaf(s_mean[d], W[(size_t)d * R_DIM + t], acc);
        g_y[b * R_DIM + t] = acc * pw[t];
    }
}

// ---------------------------------------------------------------------------
// K3: broadcast y over the sequence axis. One float4 store per thread.
// out float4 index i: b = i >> 18 (N*R/4 = 262144), r4 = i & 31.
// ---------------------------------------------------------------------------
__global__ __launch_bounds__(256) void k3_broadcast(float4* __restrict__ out) {
    const int i = blockIdx.x * blockDim.x + threadIdx.x;   // < 2,097,152
    const int b  = i >> 18;
    const int r4 = i & (R_DIM / 4 - 1);
    const float4* y4 = reinterpret_cast<const float4*>(g_y);
    out[i] = __ldg(&y4[b * (R_DIM / 4) + r4]);
}

// ---------------------------------------------------------------------------
extern "C" void kernel_launch(void* const* d_in, const int* in_sizes, int n_in,
                              void* d_out, int out_size) {
    const float* x  = (const float*)d_in[0];
    const float* W  = (const float*)d_in[1];
    const float* pw = (const float*)d_in[2];
    float* out      = (float*)d_out;

    (void)in_sizes; (void)n_in; (void)out_size;

    dim3 g1(CHUNKS, B_DIM);
    k1_colsum_partial<<<g1, 128>>>(x);
    k2_finish_and_project<<<B_DIM, 512>>>(W, pw);

    const int total4 = B_DIM * N_DIM * R_DIM / 4;   // 2,097,152
    k3_broadcast<<<total4 / 256, 256>>>((float4*)out);
}

// round 2
// speedup vs baseline: 1.4678x; 1.4678x over previous
#include <cuda_runtime.h>
#include <cuda_bf16.h>

// EfficientReynoldsFeatureOperator:
//   x:  (B=8, N=8192, D=512) fp32
//   W:  (D=512, R=128)       fp32
//   pw: (R=128)              fp32
//   out:(B, N, R) fp32,  out[b,n,r] = (mean_n(x[b]) @ W)[r] * pw[r]
// Using mean_n(x @ W) == (mean_n x) @ W.

#define B_DIM 8
#define N_DIM 8192
#define D_DIM 512
#define R_DIM 128
#define CHUNKS 256                          // n-chunks per batch (round 1: 128)
#define ROWS_PER_CHUNK (N_DIM / CHUNKS)     // 32

__device__ float g_partial[B_DIM * CHUNKS * D_DIM];   // 4 MB scratch
__device__ float g_y[B_DIM * R_DIM];                  // 4 KB

// ---------------------------------------------------------------------------
// K1: partial column sums of x over n.
// grid = (CHUNKS, B) = 2048 blocks, 128 threads; thread t owns float4 slot t.
// 2048 blocks -> ~55 warps/SM resident; unroll 8 for per-thread MLP.
// ---------------------------------------------------------------------------
__global__ __launch_bounds__(128) void k1_colsum_partial(const float* __restrict__ x) {
    const int chunk = blockIdx.x;
    const int b     = blockIdx.y;
    const int d4    = threadIdx.x;            // 0..127

    const float4* xrow = reinterpret_cast<const float4*>(
        x + (size_t)(b * N_DIM + chunk * ROWS_PER_CHUNK) * D_DIM);

    float4 a0 = make_float4(0.f, 0.f, 0.f, 0.f);
    float4 a1 = make_float4(0.f, 0.f, 0.f, 0.f);
#pragma unroll 8
    for (int i = 0; i < ROWS_PER_CHUNK; i += 2) {
        float4 v0 = xrow[(size_t)i       * (D_DIM / 4) + d4];
        float4 v1 = xrow[(size_t)(i + 1) * (D_DIM / 4) + d4];
        a0.x += v0.x; a0.y += v0.y; a0.z += v0.z; a0.w += v0.w;
        a1.x += v1.x; a1.y += v1.y; a1.z += v1.z; a1.w += v1.w;
    }
    a0.x += a1.x; a0.y += a1.y; a0.z += a1.z; a0.w += a1.w;

    float4* p = reinterpret_cast<float4*>(
        g_partial + (size_t)(b * CHUNKS + chunk) * D_DIM);
    p[d4] = a0;
}

// ---------------------------------------------------------------------------
// K2: per batch, finish the reduction, then y[b,r] = (mean @ W)[r] * pw[r].
// grid = B, 512 threads.
//   Phase 1: thread t sums CHUNKS partials for d=t (coalesced, unroll 16).
//   Phase 2: warp w owns d-slice [32w, 32w+32); lanes own r (coalesced W
//            reads); 4 accumulators cover r = lane + {0,32,64,96}.
//   Phase 3: smem reduce 16 warp-partials per r.
// ---------------------------------------------------------------------------
__global__ __launch_bounds__(512) void k2_finish_and_project(
    const float* __restrict__ W, const float* __restrict__ pw) {
    __shared__ float s_mean[D_DIM];
    __shared__ float s_red[16][R_DIM];
    const int b = blockIdx.x;
    const int t = threadIdx.x;

    float s = 0.f;
    const float* base = g_partial + (size_t)b * CHUNKS * D_DIM + t;
#pragma unroll 16
    for (int c = 0; c < CHUNKS; ++c)
        s += base[(size_t)c * D_DIM];
    s_mean[t] = s * (1.0f / (float)N_DIM);
    __syncthreads();

    const int w    = t >> 5;
    const int lane = t & 31;
    float acc0 = 0.f, acc1 = 0.f, acc2 = 0.f, acc3 = 0.f;
#pragma unroll
    for (int i = 0; i < 32; ++i) {
        const int d = w * 32 + i;
        const float m = s_mean[d];
        const float* Wr = W + (size_t)d * R_DIM;
        acc0 = fmaf(m, __ldg(&Wr[lane]),      acc0);
        acc1 = fmaf(m, __ldg(&Wr[32 + lane]), acc1);
        acc2 = fmaf(m, __ldg(&Wr[64 + lane]), acc2);
        acc3 = fmaf(m, __ldg(&Wr[96 + lane]), acc3);
    }
    s_red[w][lane]      = acc0;
    s_red[w][32 + lane] = acc1;
    s_red[w][64 + lane] = acc2;
    s_red[w][96 + lane] = acc3;
    __syncthreads();

    if (t < R_DIM) {
        float y = 0.f;
#pragma unroll
        for (int k = 0; k < 16; ++k)
            y += s_red[k][t];
        g_y[b * R_DIM + t] = y * pw[t];
    }
}

// ---------------------------------------------------------------------------
// K3: broadcast y over the sequence axis. One float4 store per thread.
// ---------------------------------------------------------------------------
__global__ __launch_bounds__(256) void k3_broadcast(float4* __restrict__ out) {
    const int i = blockIdx.x * blockDim.x + threadIdx.x;   // < 2,097,152
    const int b  = i >> 18;                                // N*R/4 = 262144
    const int r4 = i & (R_DIM / 4 - 1);
    const float4* y4 = reinterpret_cast<const float4*>(g_y);
    out[i] = __ldg(&y4[b * (R_DIM / 4) + r4]);
}

// ---------------------------------------------------------------------------
extern "C" void kernel_launch(void* const* d_in, const int* in_sizes, int n_in,
                              void* d_out, int out_size) {
    const float* x  = (const float*)d_in[0];
    const float* W  = (const float*)d_in[1];
    const float* pw = (const float*)d_in[2];
    float* out      = (float*)d_out;

    (void)in_sizes; (void)n_in; (void)out_size;

    dim3 g1(CHUNKS, B_DIM);
    k1_colsum_partial<<<g1, 128>>>(x);
    k2_finish_and_project<<<B_DIM, 512>>>(W, pw);

    const int total4 = B_DIM * N_DIM * R_DIM / 4;   // 2,097,152
    k3_broadcast<<<total4 / 256, 256>>>((float4*)out);
}

// round 3
// speedup vs baseline: 1.8176x; 1.2383x over previous
#include <cuda_runtime.h>
#include <cuda_bf16.h>

// EfficientReynoldsFeatureOperator:
//   x:  (B=8, N=8192, D=512) fp32
//   W:  (D=512, R=128)       fp32
//   pw: (R=128)              fp32
//   out:(B, N, R) fp32,  out[b,n,r] = (mean_n(x[b]) @ W)[r] * pw[r]
// Using mean_n(x @ W) == (mean_n x) @ W.

#define B_DIM 8
#define N_DIM 8192
#define D_DIM 512
#define R_DIM 128
#define CHUNKS 256
#define ROWS_PER_CHUNK (N_DIM / CHUNKS)     // 32

__device__ float g_partial[B_DIM * CHUNKS * D_DIM];   // 4 MB scratch
__device__ float g_y[B_DIM * R_DIM];                  // 4 KB

// ---------------------------------------------------------------------------
// K1: partial column sums of x over n.
// grid = (CHUNKS, B) = 2048 blocks, 128 threads; thread t owns float4 slot t.
// 64-reg budget (launch_bounds .,8) so ptxas can front-batch ~12 LDG.128 —
// round 2 showed regs=32 capped MLP at ~4 and pinned BW at 4.9 TB/s.
// __ldcs: x is read-once, skip L2 retention.
// ---------------------------------------------------------------------------
__global__ __launch_bounds__(128, 8) void k1_colsum_partial(const float* __restrict__ x) {
    const int chunk = blockIdx.x;
    const int b     = blockIdx.y;
    const int d4    = threadIdx.x;            // 0..127

    const float4* xrow = reinterpret_cast<const float4*>(
        x + (size_t)(b * N_DIM + chunk * ROWS_PER_CHUNK) * D_DIM);

    float4 a0 = make_float4(0.f, 0.f, 0.f, 0.f);
    float4 a1 = make_float4(0.f, 0.f, 0.f, 0.f);
    float4 a2 = make_float4(0.f, 0.f, 0.f, 0.f);
    float4 a3 = make_float4(0.f, 0.f, 0.f, 0.f);

#pragma unroll
    for (int i = 0; i < ROWS_PER_CHUNK; i += 4) {
        float4 v0 = __ldcs(&xrow[(size_t)(i + 0) * (D_DIM / 4) + d4]);
        float4 v1 = __ldcs(&xrow[(size_t)(i + 1) * (D_DIM / 4) + d4]);
        float4 v2 = __ldcs(&xrow[(size_t)(i + 2) * (D_DIM / 4) + d4]);
        float4 v3 = __ldcs(&xrow[(size_t)(i + 3) * (D_DIM / 4) + d4]);
        a0.x += v0.x; a0.y += v0.y; a0.z += v0.z; a0.w += v0.w;
        a1.x += v1.x; a1.y += v1.y; a1.z += v1.z; a1.w += v1.w;
        a2.x += v2.x; a2.y += v2.y; a2.z += v2.z; a2.w += v2.w;
        a3.x += v3.x; a3.y += v3.y; a3.z += v3.z; a3.w += v3.w;
    }
    a0.x += a1.x; a0.y += a1.y; a0.z += a1.z; a0.w += a1.w;
    a2.x += a3.x; a2.y += a3.y; a2.z += a3.z; a2.w += a3.w;
    a0.x += a2.x; a0.y += a2.y; a0.z += a2.z; a0.w += a2.w;

    float4* p = reinterpret_cast<float4*>(
        g_partial + (size_t)(b * CHUNKS + chunk) * D_DIM);
    p[d4] = a0;
}

// ---------------------------------------------------------------------------
// K2: per batch: finish reduction (coalesced!), project, scale.
// grid = B, 512 threads.
//   Phase 1: group g = t>>7 (4 groups), d4 = t&127. Group g sums chunks
//            c = g, g+4, ... (64 iters, float4, fully coalesced across d4).
//   Phase 2: smem combine 4 groups -> s_mean.
//   Phase 3: warp w owns d-slice [32w,32w+32); lanes own r (coalesced W).
//   Phase 4: smem reduce 16 warp partials per r, scale by pw.
// ---------------------------------------------------------------------------
__global__ __launch_bounds__(512) void k2_finish_and_project(
    const float* __restrict__ W, const float* __restrict__ pw) {
    __shared__ float s_part[4][D_DIM];
    __shared__ float s_mean[D_DIM];
    __shared__ float s_red[16][R_DIM];
    const int b = blockIdx.x;
    const int t = threadIdx.x;
    const int g  = t >> 7;        // 0..3
    const int d4 = t & 127;       // 0..127

    const float4* pbase = reinterpret_cast<const float4*>(
        g_partial + (size_t)b * CHUNKS * D_DIM);

    float4 acc = make_float4(0.f, 0.f, 0.f, 0.f);
#pragma unroll 8
    for (int c = g; c < CHUNKS; c += 4) {
        float4 v = pbase[(size_t)c * (D_DIM / 4) + d4];
        acc.x += v.x; acc.y += v.y; acc.z += v.z; acc.w += v.w;
    }
    s_part[g][4 * d4 + 0] = acc.x;
    s_part[g][4 * d4 + 1] = acc.y;
    s_part[g][4 * d4 + 2] = acc.z;
    s_part[g][4 * d4 + 3] = acc.w;
    __syncthreads();

    s_mean[t] = (s_part[0][t] + s_part[1][t] + s_part[2][t] + s_part[3][t])
                * (1.0f / (float)N_DIM);
    __syncthreads();

    const int w    = t >> 5;
    const int lane = t & 31;
    float acc0 = 0.f, acc1 = 0.f, acc2 = 0.f, acc3 = 0.f;
#pragma unroll
    for (int i = 0; i < 32; ++i) {
        const int d = w * 32 + i;
        const float m = s_mean[d];
        const float* Wr = W + (size_t)d * R_DIM;
        acc0 = fmaf(m, __ldg(&Wr[lane]),      acc0);
        acc1 = fmaf(m, __ldg(&Wr[32 + lane]), acc1);
        acc2 = fmaf(m, __ldg(&Wr[64 + lane]), acc2);
        acc3 = fmaf(m, __ldg(&Wr[96 + lane]), acc3);
    }
    s_red[w][lane]      = acc0;
    s_red[w][32 + lane] = acc1;
    s_red[w][64 + lane] = acc2;
    s_red[w][96 + lane] = acc3;
    __syncthreads();

    if (t < R_DIM) {
        float y = 0.f;
#pragma unroll
        for (int k = 0; k < 16; ++k)
            y += s_red[k][t];
        g_y[b * R_DIM + t] = y * pw[t];
    }
}

// ---------------------------------------------------------------------------
// K3: broadcast y over the sequence axis. Streaming float4 stores.
// ---------------------------------------------------------------------------
__global__ __launch_bounds__(256) void k3_broadcast(float4* __restrict__ out) {
    const int i = blockIdx.x * blockDim.x + threadIdx.x;   // < 2,097,152
    const int b  = i >> 18;                                // N*R/4 = 262144
    const int r4 = i & (R_DIM / 4 - 1);
    const float4* y4 = reinterpret_cast<const float4*>(g_y);
    float4 v = __ldg(&y4[b * (R_DIM / 4) + r4]);
    __stcs(&out[i], v);
}

// ---------------------------------------------------------------------------
extern "C" void kernel_launch(void* const* d_in, const int* in_sizes, int n_in,
                              void* d_out, int out_size) {
    const float* x  = (const float*)d_in[0];
    const float* W  = (const float*)d_in[1];
    const float* pw = (const float*)d_in[2];
    float* out      = (float*)d_out;

    (void)in_sizes; (void)n_in; (void)out_size;

    dim3 g1(CHUNKS, B_DIM);
    k1_colsum_partial<<<g1, 128>>>(x);
    k2_finish_and_project<<<B_DIM, 512>>>(W, pw);

    const int total4 = B_DIM * N_DIM * R_DIM / 4;   // 2,097,152
    k3_broadcast<<<total4 / 256, 256>>>((float4*)out);
}

// round 4
// speedup vs baseline: 1.9654x; 1.0813x over previous
#include <cuda_runtime.h>
#include <cuda_bf16.h>

// EfficientReynoldsFeatureOperator:
//   x:  (B=8, N=8192, D=512) fp32
//   W:  (D=512, R=128)       fp32
//   pw: (R=128)              fp32
//   out:(B, N, R) fp32,  out[b,n,r] = (mean_n(x[b]) @ W)[r] * pw[r]
// Using mean_n(x @ W) == (mean_n x) @ W.

#define B_DIM 8
#define N_DIM 8192
#define D_DIM 512
#define R_DIM 128
#define CHUNKS 256
#define ROWS_PER_CHUNK (N_DIM / CHUNKS)     // 32
#define G2 32                                // k2a blocks per batch
#define CHUNKS_PER_G2 (CHUNKS / G2)          // 8

__device__ float g_partial[B_DIM * CHUNKS * D_DIM];   // 4 MB scratch (L2-hot)
__device__ float g_p2[B_DIM * G2 * D_DIM];            // 512 KB
__device__ float g_y[B_DIM * R_DIM];                  // 4 KB

// ---------------------------------------------------------------------------
// K1: partial column sums of x over n.
// grid = (CHUNKS, B) = 2048 blocks, 128 threads; thread t owns float4 slot t.
// 8 back-to-back LDG.128 per batch (MLP_p1=8), 2 accumulators -> fits 64 regs.
// __ldcs: x is read-once, evict-first.
// ---------------------------------------------------------------------------
__global__ __launch_bounds__(128, 8) void k1_colsum_partial(const float* __restrict__ x) {
    const int chunk = blockIdx.x;
    const int b     = blockIdx.y;
    const int d4    = threadIdx.x;            // 0..127

    const float4* xrow = reinterpret_cast<const float4*>(
        x + (size_t)(b * N_DIM + chunk * ROWS_PER_CHUNK) * D_DIM);

    float4 a0 = make_float4(0.f, 0.f, 0.f, 0.f);
    float4 a1 = make_float4(0.f, 0.f, 0.f, 0.f);

#pragma unroll
    for (int i = 0; i < ROWS_PER_CHUNK; i += 8) {
        float4 v0 = __ldcs(&xrow[(size_t)(i + 0) * (D_DIM / 4) + d4]);
        float4 v1 = __ldcs(&xrow[(size_t)(i + 1) * (D_DIM / 4) + d4]);
        float4 v2 = __ldcs(&xrow[(size_t)(i + 2) * (D_DIM / 4) + d4]);
        float4 v3 = __ldcs(&xrow[(size_t)(i + 3) * (D_DIM / 4) + d4]);
        float4 v4 = __ldcs(&xrow[(size_t)(i + 4) * (D_DIM / 4) + d4]);
        float4 v5 = __ldcs(&xrow[(size_t)(i + 5) * (D_DIM / 4) + d4]);
        float4 v6 = __ldcs(&xrow[(size_t)(i + 6) * (D_DIM / 4) + d4]);
        float4 v7 = __ldcs(&xrow[(size_t)(i + 7) * (D_DIM / 4) + d4]);
        a0.x += v0.x; a0.y += v0.y; a0.z += v0.z; a0.w += v0.w;
        a1.x += v1.x; a1.y += v1.y; a1.z += v1.z; a1.w += v1.w;
        a0.x += v2.x; a0.y += v2.y; a0.z += v2.z; a0.w += v2.w;
        a1.x += v3.x; a1.y += v3.y; a1.z += v3.z; a1.w += v3.w;
        a0.x += v4.x; a0.y += v4.y; a0.z += v4.z; a0.w += v4.w;
        a1.x += v5.x; a1.y += v5.y; a1.z += v5.z; a1.w += v5.w;
        a0.x += v6.x; a0.y += v6.y; a0.z += v6.z; a0.w += v6.w;
        a1.x += v7.x; a1.y += v7.y; a1.z += v7.z; a1.w += v7.w;
    }
    a0.x += a1.x; a0.y += a1.y; a0.z += a1.z; a0.w += a1.w;

    float4* p = reinterpret_cast<float4*>(
        g_partial + (size_t)(b * CHUNKS + chunk) * D_DIM);
    p[d4] = a0;
}

// ---------------------------------------------------------------------------
// K2a: first-level partial reduction, spread across 256 blocks.
// grid = (G2, B); block (j,b) sums contiguous chunks [8j, 8j+8) -> g_p2.
// All loads coalesced float4, L2-hot (just written by k1).
// ---------------------------------------------------------------------------
__global__ __launch_bounds__(128) void k2a_reduce(void) {
    const int j  = blockIdx.x;
    const int b  = blockIdx.y;
    const int d4 = threadIdx.x;

    const float4* base = reinterpret_cast<const float4*>(
        g_partial + (size_t)(b * CHUNKS + j * CHUNKS_PER_G2) * D_DIM);

    float4 acc = make_float4(0.f, 0.f, 0.f, 0.f);
#pragma unroll
    for (int c = 0; c < CHUNKS_PER_G2; ++c) {
        float4 v = base[(size_t)c * (D_DIM / 4) + d4];
        acc.x += v.x; acc.y += v.y; acc.z += v.z; acc.w += v.w;
    }
    float4* p = reinterpret_cast<float4*>(
        g_p2 + (size_t)(b * G2 + j) * D_DIM);
    p[d4] = acc;
}

// ---------------------------------------------------------------------------
// K2b: per batch: finish reduction (32 partials), project, scale.
// grid = B, 512 threads.
// ---------------------------------------------------------------------------
__global__ __launch_bounds__(512) void k2b_finish_and_project(
    const float* __restrict__ W, const float* __restrict__ pw) {
    __shared__ float s_part[4][D_DIM];
    __shared__ float s_mean[D_DIM];
    __shared__ float s_red[16][R_DIM];
    const int b = blockIdx.x;
    const int t = threadIdx.x;
    const int g  = t >> 7;        // 0..3
    const int d4 = t & 127;       // 0..127

    const float4* pbase = reinterpret_cast<const float4*>(
        g_p2 + (size_t)b * G2 * D_DIM);

    float4 acc = make_float4(0.f, 0.f, 0.f, 0.f);
#pragma unroll
    for (int c = g; c < G2; c += 4) {
        float4 v = pbase[(size_t)c * (D_DIM / 4) + d4];
        acc.x += v.x; acc.y += v.y; acc.z += v.z; acc.w += v.w;
    }
    s_part[g][4 * d4 + 0] = acc.x;
    s_part[g][4 * d4 + 1] = acc.y;
    s_part[g][4 * d4 + 2] = acc.z;
    s_part[g][4 * d4 + 3] = acc.w;
    __syncthreads();

    s_mean[t] = (s_part[0][t] + s_part[1][t] + s_part[2][t] + s_part[3][t])
                * (1.0f / (float)N_DIM);
    __syncthreads();

    const int w    = t >> 5;
    const int lane = t & 31;
    float acc0 = 0.f, acc1 = 0.f, acc2 = 0.f, acc3 = 0.f;
#pragma unroll
    for (int i = 0; i < 32; ++i) {
        const int d = w * 32 + i;
        const float m = s_mean[d];
        const float* Wr = W + (size_t)d * R_DIM;
        acc0 = fmaf(m, __ldg(&Wr[lane]),      acc0);
        acc1 = fmaf(m, __ldg(&Wr[32 + lane]), acc1);
        acc2 = fmaf(m, __ldg(&Wr[64 + lane]), acc2);
        acc3 = fmaf(m, __ldg(&Wr[96 + lane]), acc3);
    }
    s_red[w][lane]      = acc0;
    s_red[w][32 + lane] = acc1;
    s_red[w][64 + lane] = acc2;
    s_red[w][96 + lane] = acc3;
    __syncthreads();

    if (t < R_DIM) {
        float y = 0.f;
#pragma unroll
        for (int k = 0; k < 16; ++k)
            y += s_red[k][t];
        g_y[b * R_DIM + t] = y * pw[t];
    }
}

// ---------------------------------------------------------------------------
// K3: broadcast y over the sequence axis. Streaming float4 stores.
// ---------------------------------------------------------------------------
__global__ __launch_bounds__(256) void k3_broadcast(float4* __restrict__ out) {
    const int i = blockIdx.x * blockDim.x + threadIdx.x;   // < 2,097,152
    const int b  = i >> 18;                                // N*R/4 = 262144
    const int r4 = i & (R_DIM / 4 - 1);
    const float4* y4 = reinterpret_cast<const float4*>(g_y);
    float4 v = __ldg(&y4[b * (R_DIM / 4) + r4]);
    __stcs(&out[i], v);
}

// ---------------------------------------------------------------------------
extern "C" void kernel_launch(void* const* d_in, const int* in_sizes, int n_in,
                              void* d_out, int out_size) {
    const float* x  = (const float*)d_in[0];
    const float* W  = (const float*)d_in[1];
    const float* pw = (const float*)d_in[2];
    float* out      = (float*)d_out;

    (void)in_sizes; (void)n_in; (void)out_size;

    dim3 g1(CHUNKS, B_DIM);
    k1_colsum_partial<<<g1, 128>>>(x);

    dim3 g2a(G2, B_DIM);
    k2a_reduce<<<g2a, 128>>>();

    k2b_finish_and_project<<<B_DIM, 512>>>(W, pw);

    const int total4 = B_DIM * N_DIM * R_DIM / 4;   // 2,097,152
    k3_broadcast<<<total4 / 256, 256>>>((float4*)out);
}

// round 5
// speedup vs baseline: 2.0207x; 1.0281x over previous
#include <cuda_runtime.h>
#include <cuda_bf16.h>

// EfficientReynoldsFeatureOperator:
//   x:  (B=8, N=8192, D=512) fp32
//   W:  (D=512, R=128)       fp32
//   pw: (R=128)              fp32
//   out:(B, N, R) fp32,  out[b,n,r] = (mean_n(x[b]) @ W)[r] * pw[r]
// Using mean_n(x @ W) == (mean_n x) @ W.

#define B_DIM 8
#define N_DIM 8192
#define D_DIM 512
#define R_DIM 128
#define CHUNKS 256
#define ROWS_PER_CHUNK (N_DIM / CHUNKS)     // 32
#define G2 32                                // k2a blocks per batch
#define CHUNKS_PER_G2 (CHUNKS / G2)          // 8

__device__ float g_partial[B_DIM * CHUNKS * D_DIM];   // 4 MB scratch (L2-hot)
__device__ float g_p2[B_DIM * G2 * D_DIM];            // 512 KB
__device__ float g_y[B_DIM * R_DIM];                  // 4 KB

// ---------------------------------------------------------------------------
// K1: partial column sums of x over n.
// grid = (CHUNKS, B) = 2048 blocks, 128 threads; thread t owns float4 slot t.
// 8 back-to-back LDG.128 per batch (MLP_p1=8), 2 accumulators -> fits 64 regs.
// __ldcs: x is read-once, evict-first.
// ---------------------------------------------------------------------------
__global__ __launch_bounds__(128, 8) void k1_colsum_partial(const float* __restrict__ x) {
    const int chunk = blockIdx.x;
    const int b     = blockIdx.y;
    const int d4    = threadIdx.x;            // 0..127

    const float4* xrow = reinterpret_cast<const float4*>(
        x + (size_t)(b * N_DIM + chunk * ROWS_PER_CHUNK) * D_DIM);

    float4 a0 = make_float4(0.f, 0.f, 0.f, 0.f);
    float4 a1 = make_float4(0.f, 0.f, 0.f, 0.f);

#pragma unroll
    for (int i = 0; i < ROWS_PER_CHUNK; i += 8) {
        float4 v0 = __ldcs(&xrow[(size_t)(i + 0) * (D_DIM / 4) + d4]);
        float4 v1 = __ldcs(&xrow[(size_t)(i + 1) * (D_DIM / 4) + d4]);
        float4 v2 = __ldcs(&xrow[(size_t)(i + 2) * (D_DIM / 4) + d4]);
        float4 v3 = __ldcs(&xrow[(size_t)(i + 3) * (D_DIM / 4) + d4]);
        float4 v4 = __ldcs(&xrow[(size_t)(i + 4) * (D_DIM / 4) + d4]);
        float4 v5 = __ldcs(&xrow[(size_t)(i + 5) * (D_DIM / 4) + d4]);
        float4 v6 = __ldcs(&xrow[(size_t)(i + 6) * (D_DIM / 4) + d4]);
        float4 v7 = __ldcs(&xrow[(size_t)(i + 7) * (D_DIM / 4) + d4]);
        a0.x += v0.x; a0.y += v0.y; a0.z += v0.z; a0.w += v0.w;
        a1.x += v1.x; a1.y += v1.y; a1.z += v1.z; a1.w += v1.w;
        a0.x += v2.x; a0.y += v2.y; a0.z += v2.z; a0.w += v2.w;
        a1.x += v3.x; a1.y += v3.y; a1.z += v3.z; a1.w += v3.w;
        a0.x += v4.x; a0.y += v4.y; a0.z += v4.z; a0.w += v4.w;
        a1.x += v5.x; a1.y += v5.y; a1.z += v5.z; a1.w += v5.w;
        a0.x += v6.x; a0.y += v6.y; a0.z += v6.z; a0.w += v6.w;
        a1.x += v7.x; a1.y += v7.y; a1.z += v7.z; a1.w += v7.w;
    }
    a0.x += a1.x; a0.y += a1.y; a0.z += a1.z; a0.w += a1.w;

    float4* p = reinterpret_cast<float4*>(
        g_partial + (size_t)(b * CHUNKS + chunk) * D_DIM);
    p[d4] = a0;
}

// ---------------------------------------------------------------------------
// K2a: first-level partial reduction, spread across 256 blocks.
// grid = (G2, B); block (j,b) sums contiguous chunks [8j, 8j+8) -> g_p2.
// All loads coalesced float4, L2-hot (just written by k1).
// ---------------------------------------------------------------------------
__global__ __launch_bounds__(128) void k2a_reduce(void) {
    const int j  = blockIdx.x;
    const int b  = blockIdx.y;
    const int d4 = threadIdx.x;

    const float4* base = reinterpret_cast<const float4*>(
        g_partial + (size_t)(b * CHUNKS + j * CHUNKS_PER_G2) * D_DIM);

    float4 acc = make_float4(0.f, 0.f, 0.f, 0.f);
#pragma unroll
    for (int c = 0; c < CHUNKS_PER_G2; ++c) {
        float4 v = base[(size_t)c * (D_DIM / 4) + d4];
        acc.x += v.x; acc.y += v.y; acc.z += v.z; acc.w += v.w;
    }
    float4* p = reinterpret_cast<float4*>(
        g_p2 + (size_t)(b * G2 + j) * D_DIM);
    p[d4] = acc;
}

// ---------------------------------------------------------------------------
// K2b: per batch: finish reduction (32 partials), project, scale.
// grid = B, 512 threads.
// ---------------------------------------------------------------------------
__global__ __launch_bounds__(512) void k2b_finish_and_project(
    const float* __restrict__ W, const float* __restrict__ pw) {
    __shared__ float s_part[4][D_DIM];
    __shared__ float s_mean[D_DIM];
    __shared__ float s_red[16][R_DIM];
    const int b = blockIdx.x;
    const int t = threadIdx.x;
    const int g  = t >> 7;        // 0..3
    const int d4 = t & 127;       // 0..127

    const float4* pbase = reinterpret_cast<const float4*>(
        g_p2 + (size_t)b * G2 * D_DIM);

    float4 acc = make_float4(0.f, 0.f, 0.f, 0.f);
#pragma unroll
    for (int c = g; c < G2; c += 4) {
        float4 v = pbase[(size_t)c * (D_DIM / 4) + d4];
        acc.x += v.x; acc.y += v.y; acc.z += v.z; acc.w += v.w;
    }
    s_part[g][4 * d4 + 0] = acc.x;
    s_part[g][4 * d4 + 1] = acc.y;
    s_part[g][4 * d4 + 2] = acc.z;
    s_part[g][4 * d4 + 3] = acc.w;
    __syncthreads();

    s_mean[t] = (s_part[0][t] + s_part[1][t] + s_part[2][t] + s_part[3][t])
                * (1.0f / (float)N_DIM);
    __syncthreads();

    const int w    = t >> 5;
    const int lane = t & 31;
    float acc0 = 0.f, acc1 = 0.f, acc2 = 0.f, acc3 = 0.f;
#pragma unroll
    for (int i = 0; i < 32; ++i) {
        const int d = w * 32 + i;
        const float m = s_mean[d];
        const float* Wr = W + (size_t)d * R_DIM;
        acc0 = fmaf(m, __ldg(&Wr[lane]),      acc0);
        acc1 = fmaf(m, __ldg(&Wr[32 + lane]), acc1);
        acc2 = fmaf(m, __ldg(&Wr[64 + lane]), acc2);
        acc3 = fmaf(m, __ldg(&Wr[96 + lane]), acc3);
    }
    s_red[w][lane]      = acc0;
    s_red[w][32 + lane] = acc1;
    s_red[w][64 + lane] = acc2;
    s_red[w][96 + lane] = acc3;
    __syncthreads();

    if (t < R_DIM) {
        float y = 0.f;
#pragma unroll
        for (int k = 0; k < 16; ++k)
            y += s_red[k][t];
        g_y[b * R_DIM + t] = y * pw[t];
    }
}

// ---------------------------------------------------------------------------
// K3: broadcast y over the sequence axis.
// Round-4 ncu: DRAM=0% (out fits in L2), issue-bound at 1 store/thread.
// Now: 1024 blocks x 256 thr; thread owns float4 slot `tid` in every batch.
// Stride between iterations = N*R/4 = 262144, so r4 = tid & 31 is invariant
// and b walks 0..7 -> 8 independent coalesced STG.128 per thread (ILP=8).
// ---------------------------------------------------------------------------
__global__ __launch_bounds__(256) void k3_broadcast(float4* __restrict__ out) {
    const int tid = blockIdx.x * blockDim.x + threadIdx.x;  // 0..262143
    const int r4  = tid & (R_DIM / 4 - 1);
    const float4* y4 = reinterpret_cast<const float4*>(g_y);
#pragma unroll
    for (int b = 0; b < B_DIM; ++b) {
        float4 v = __ldg(&y4[b * (R_DIM / 4) + r4]);
        out[(size_t)b * (N_DIM * R_DIM / 4) + tid] = v;
    }
}

// ---------------------------------------------------------------------------
extern "C" void kernel_launch(void* const* d_in, const int* in_sizes, int n_in,
                              void* d_out, int out_size) {
    const float* x  = (const float*)d_in[0];
    const float* W  = (const float*)d_in[1];
    const float* pw = (const float*)d_in[2];
    float* out      = (float*)d_out;

    (void)in_sizes; (void)n_in; (void)out_size;

    dim3 g1(CHUNKS, B_DIM);
    k1_colsum_partial<<<g1, 128>>>(x);

    dim3 g2a(G2, B_DIM);
    k2a_reduce<<<g2a, 128>>>();

    k2b_finish_and_project<<<B_DIM, 512>>>(W, pw);

    const int perBatch4 = N_DIM * R_DIM / 4;   // 262144
    k3_broadcast<<<perBatch4 / 256, 256>>>((float4*)out);
}